// round 12
// baseline (speedup 1.0000x reference)
#include <cuda_runtime.h>

typedef unsigned long long u64;

__device__ __forceinline__ u64 pk2(float lo, float hi) {
    u64 r;
    asm("mov.b64 %0, {%1, %2};" : "=l"(r)
        : "r"(__float_as_uint(lo)), "r"(__float_as_uint(hi)));
    return r;
}
__device__ __forceinline__ u64 ffma2(u64 a, u64 b, u64 c) {
    u64 d;
    asm("fma.rn.f32x2 %0, %1, %2, %3;" : "=l"(d) : "l"(a), "l"(b), "l"(c));
    return d;
}
__device__ __forceinline__ float f2lo(u64 v) { return __uint_as_float((unsigned)v); }
__device__ __forceinline__ float f2hi(u64 v) { return __uint_as_float((unsigned)(v >> 32)); }
__device__ __forceinline__ u64 d2u(double d) { return (u64)__double_as_longlong(d); }

#define MAX_B 16384
// h1 scratch, TRANSPOSED: [sample][hw = h*5+w][ld = l*5+d], channel-paired float2.
__device__ float2 g_h1[(size_t)MAX_B * 625];

// ================= kernel 1: layer 1 =================
// 5 samples / 128-thr block; thread=(l,d) computes all 5x5 (h,w) outputs,
// channels (oc0,oc1) packed in f32x2. 125/128 lanes active.
__global__ __launch_bounds__(128)
void l1_kernel(const float* __restrict__ x,
               const float* __restrict__ w1, const float* __restrict__ b1,
               int nsamp)
{
    __shared__ float xs[5][2401];
    __shared__ __align__(16) float2 w1p[9][10];   // [plane][tap pad] (oc0,oc1)
    __shared__ float2 b1p;

    const int t  = threadIdx.x;
    const int s0 = blockIdx.x * 5;

    for (int i = t; i < 81; i += 128) {
        int pl = i / 9, tp = i - pl * 9;
        w1p[pl][tp] = make_float2(w1[i], w1[81 + i]);
    }
    if (t == 0) b1p = make_float2(b1[0], b1[1]);

    {
        int nsm = nsamp - s0; if (nsm > 5) nsm = 5;
        int lim = nsm * 2401;
        const float* xb = x + (size_t)s0 * 2401;
        for (int i = t; i < lim; i += 128) ((float*)xs)[i] = xb[i];
    }
    __syncthreads();

    const int s   = t / 25;
    const int tid = t - s * 25;
    if (t < 125 && s0 + s < nsamp) {
        const int l = tid / 5, d = tid - (tid / 5) * 5;

        const u64 bb = d2u(*(const double*)&b1p);
        u64 acc[5][5];
        #pragma unroll
        for (int h = 0; h < 5; h++)
            #pragma unroll
            for (int p = 0; p < 5; p++) acc[h][p] = bb;

        #pragma unroll
        for (int i = 0; i < 3; i++)
        #pragma unroll
        for (int j = 0; j < 3; j++) {
            const int pl = i * 3 + j;
            u64 wr[9];
            {
                const double2* wv = (const double2*)&w1p[pl][0];
                double2 a0 = wv[0], a1 = wv[1], a2 = wv[2], a3 = wv[3];
                wr[0] = d2u(a0.x); wr[1] = d2u(a0.y);
                wr[2] = d2u(a1.x); wr[3] = d2u(a1.y);
                wr[4] = d2u(a2.x); wr[5] = d2u(a2.y);
                wr[6] = d2u(a3.x); wr[7] = d2u(a3.y);
                wr[8] = d2u(*(const double*)&w1p[pl][8]);
            }
            const float* pb = &xs[s][0] + (l + i) * 343 + (d + j) * 49;
            #pragma unroll
            for (int r = 0; r < 7; r++) {
                const float* rp = pb + r * 7;
                u64 xx[7];
                #pragma unroll
                for (int q = 0; q < 7; q++) { float v = rp[q]; xx[q] = pk2(v, v); }
                #pragma unroll
                for (int k = 0; k < 3; k++) {
                    const int h = r - k;
                    if (h >= 0 && h <= 4) {
                        #pragma unroll
                        for (int m = 0; m < 3; m++) {
                            const u64 w = wr[k * 3 + m];
                            #pragma unroll
                            for (int p = 0; p < 5; p++)
                                acc[h][p] = ffma2(xx[p + m], w, acc[h][p]);
                        }
                    }
                }
            }
        }

        float2* hb = &g_h1[(size_t)(s0 + s) * 625 + (size_t)(l * 5 + d)];
        #pragma unroll
        for (int h = 0; h < 5; h++)
            #pragma unroll
            for (int p = 0; p < 5; p++)
                hb[(h * 5 + p) * 25] = make_float2(fmaxf(f2lo(acc[h][p]), 0.f),
                                                   fmaxf(f2hi(acc[h][p]), 0.f));
    }
}

// ================= kernel 2: layer 2 =================
// 14 samples / 128-thr block; thread=(l,d) computes 4 oc x 3 h x 3 w = 36
// outputs. hh loaded once per hw-row, reused across all k and oc.
// f32x2 lanes = (ic0,ic1) partials. Dynamic smem (~71 KB).
#define L2_SAMP 14
__global__ __launch_bounds__(128, 3)
void l2_kernel(const float* __restrict__ w2, const float* __restrict__ b2,
               float* __restrict__ out, int nsamp)
{
    extern __shared__ char l2sm[];
    float2* h1s = (float2*)l2sm;                               // [L2_SAMP][625]
    float2* w2p = (float2*)(l2sm + L2_SAMP * 625 * 8);         // [oc][plane][tap pad 10]
    float*  b2s = (float*)(l2sm + L2_SAMP * 625 * 8 + 360 * 8);

    const int t  = threadIdx.x;
    const int s0 = blockIdx.x * L2_SAMP;

    for (int i = t; i < 324; i += 128) {
        int oc = i / 81, rr = i - oc * 81;
        int pl = rr / 9, tp = rr - pl * 9;
        w2p[oc * 90 + pl * 10 + tp] =
            make_float2(w2[oc * 162 + rr], w2[oc * 162 + 81 + rr]);
    }
    if (t < 4) b2s[t] = b2[t];

    {
        int nsm = nsamp - s0; if (nsm > L2_SAMP) nsm = L2_SAMP;
        int tot = nsm * 625;
        const float2* hg = &g_h1[(size_t)s0 * 625];
        for (int i = t; i < tot; i += 128) h1s[i] = hg[i];
    }
    __syncthreads();

    const int s   = t / 9;
    const int tid = t - s * 9;
    if (t < 126 && s0 + s < nsamp) {
        const int l = tid / 3, d = tid - l * 3;

        u64 acc[4][3][3];                       // [oc][h][w]
        #pragma unroll
        for (int oc = 0; oc < 4; oc++) {
            u64 ini = pk2(b2s[oc], 0.f);
            #pragma unroll
            for (int h = 0; h < 3; h++)
                #pragma unroll
                for (int p = 0; p < 3; p++) acc[oc][h][p] = ini;
        }

        #pragma unroll
        for (int i = 0; i < 3; i++)
        #pragma unroll
        for (int j = 0; j < 3; j++) {
            const int pl  = i * 3 + j;
            const int ldp = (l + i) * 5 + (d + j);
            const float2* vb = h1s + s * 625 + ldp;

            // all 4 oc's 9 taps for this plane (broadcast loads)
            u64 wr[4][9];
            #pragma unroll
            for (int oc = 0; oc < 4; oc++) {
                const double2* wv = (const double2*)(w2p + oc * 90 + pl * 10);
                double2 a0 = wv[0], a1 = wv[1], a2 = wv[2], a3 = wv[3];
                wr[oc][0] = d2u(a0.x); wr[oc][1] = d2u(a0.y);
                wr[oc][2] = d2u(a1.x); wr[oc][3] = d2u(a1.y);
                wr[oc][4] = d2u(a2.x); wr[oc][5] = d2u(a2.y);
                wr[oc][6] = d2u(a3.x); wr[oc][7] = d2u(a3.y);
                wr[oc][8] = d2u(*(const double*)(w2p + oc * 90 + pl * 10 + 8));
            }

            #pragma unroll
            for (int r = 0; r < 5; r++) {
                u64 hh[5];
                #pragma unroll
                for (int q = 0; q < 5; q++)
                    hh[q] = d2u(*(const double*)(vb + (r * 5 + q) * 25));
                #pragma unroll
                for (int k = 0; k < 3; k++) {
                    const int h = r - k;
                    if (h >= 0 && h <= 2) {
                        #pragma unroll
                        for (int oc = 0; oc < 4; oc++)
                        #pragma unroll
                        for (int m = 0; m < 3; m++) {
                            const u64 w = wr[oc][k * 3 + m];
                            #pragma unroll
                            for (int p = 0; p < 3; p++)
                                acc[oc][h][p] = ffma2(hh[p + m], w, acc[oc][h][p]);
                        }
                    }
                }
            }
        }

        float* ob = out + (size_t)(s0 + s) * 324;
        #pragma unroll
        for (int oc = 0; oc < 4; oc++)
            #pragma unroll
            for (int h = 0; h < 3; h++)
                #pragma unroll
                for (int p = 0; p < 3; p++)
                    ob[oc * 81 + ((l * 3 + d) * 3 + h) * 3 + p] =
                        fmaxf(f2lo(acc[oc][h][p]) + f2hi(acc[oc][h][p]), 0.f);
    }
}

extern "C" void kernel_launch(void* const* d_in, const int* in_sizes, int n_in,
                              void* d_out, int out_size) {
    const float* x  = (const float*)d_in[0];
    const float* w1 = (const float*)d_in[1];
    const float* b1 = (const float*)d_in[2];
    const float* w2 = (const float*)d_in[3];
    const float* b2 = (const float*)d_in[4];
    float* out = (float*)d_out;

    int n = in_sizes[0] / 2401;              // B
    if (n > MAX_B) n = MAX_B;

    const int l2_smem = L2_SAMP * 625 * 8 + 360 * 8 + 16;
    cudaFuncSetAttribute(l2_kernel, cudaFuncAttributeMaxDynamicSharedMemorySize,
                         l2_smem);

    l1_kernel<<<(n + 4) / 5, 128>>>(x, w1, b1, n);
    l2_kernel<<<(n + L2_SAMP - 1) / L2_SAMP, 128, l2_smem>>>(w2, b2, out, n);
}

// round 13
// speedup vs baseline: 1.0696x; 1.0696x over previous
#include <cuda_runtime.h>

typedef unsigned long long u64;

__device__ __forceinline__ u64 pk2(float lo, float hi) {
    u64 r;
    asm("mov.b64 %0, {%1, %2};" : "=l"(r)
        : "r"(__float_as_uint(lo)), "r"(__float_as_uint(hi)));
    return r;
}
__device__ __forceinline__ u64 ffma2(u64 a, u64 b, u64 c) {
    u64 d;
    asm("fma.rn.f32x2 %0, %1, %2, %3;" : "=l"(d) : "l"(a), "l"(b), "l"(c));
    return d;
}
__device__ __forceinline__ float f2lo(u64 v) { return __uint_as_float((unsigned)v); }
__device__ __forceinline__ float f2hi(u64 v) { return __uint_as_float((unsigned)(v >> 32)); }
__device__ __forceinline__ u64 d2u(double d) { return (u64)__double_as_longlong(d); }

#define MAX_B 16384
// h1 scratch, TRANSPOSED: [sample][hw = h*5+w][ld = l*5+d], channel-paired float2.
__device__ float2 g_h1[(size_t)MAX_B * 625];

// ================= kernel 1: layer 1 =================
// 5 samples / 128-thr block; thread=(l,d) computes all 5x5 (h,w) outputs,
// channels (oc0,oc1) packed in f32x2. 125/128 lanes active.
__global__ __launch_bounds__(128)
void l1_kernel(const float* __restrict__ x,
               const float* __restrict__ w1, const float* __restrict__ b1,
               int nsamp)
{
    __shared__ float xs[5][2401];
    __shared__ __align__(16) float2 w1p[9][10];   // [plane][tap pad] (oc0,oc1)
    __shared__ float2 b1p;

    const int t  = threadIdx.x;
    const int s0 = blockIdx.x * 5;

    for (int i = t; i < 81; i += 128) {
        int pl = i / 9, tp = i - pl * 9;
        w1p[pl][tp] = make_float2(w1[i], w1[81 + i]);
    }
    if (t == 0) b1p = make_float2(b1[0], b1[1]);

    {
        int nsm = nsamp - s0; if (nsm > 5) nsm = 5;
        int lim = nsm * 2401;
        const float* xb = x + (size_t)s0 * 2401;
        for (int i = t; i < lim; i += 128) ((float*)xs)[i] = xb[i];
    }
    __syncthreads();

    const int s   = t / 25;
    const int tid = t - s * 25;
    if (t < 125 && s0 + s < nsamp) {
        const int l = tid / 5, d = tid - (tid / 5) * 5;

        const u64 bb = d2u(*(const double*)&b1p);
        u64 acc[5][5];
        #pragma unroll
        for (int h = 0; h < 5; h++)
            #pragma unroll
            for (int p = 0; p < 5; p++) acc[h][p] = bb;

        #pragma unroll
        for (int i = 0; i < 3; i++)
        #pragma unroll
        for (int j = 0; j < 3; j++) {
            const int pl = i * 3 + j;
            u64 wr[9];
            {
                const double2* wv = (const double2*)&w1p[pl][0];
                double2 a0 = wv[0], a1 = wv[1], a2 = wv[2], a3 = wv[3];
                wr[0] = d2u(a0.x); wr[1] = d2u(a0.y);
                wr[2] = d2u(a1.x); wr[3] = d2u(a1.y);
                wr[4] = d2u(a2.x); wr[5] = d2u(a2.y);
                wr[6] = d2u(a3.x); wr[7] = d2u(a3.y);
                wr[8] = d2u(*(const double*)&w1p[pl][8]);
            }
            const float* pb = &xs[s][0] + (l + i) * 343 + (d + j) * 49;
            #pragma unroll
            for (int r = 0; r < 7; r++) {
                const float* rp = pb + r * 7;
                u64 xx[7];
                #pragma unroll
                for (int q = 0; q < 7; q++) { float v = rp[q]; xx[q] = pk2(v, v); }
                #pragma unroll
                for (int k = 0; k < 3; k++) {
                    const int h = r - k;
                    if (h >= 0 && h <= 4) {
                        #pragma unroll
                        for (int m = 0; m < 3; m++) {
                            const u64 w = wr[k * 3 + m];
                            #pragma unroll
                            for (int p = 0; p < 5; p++)
                                acc[h][p] = ffma2(xx[p + m], w, acc[h][p]);
                        }
                    }
                }
            }
        }

        float2* hb = &g_h1[(size_t)(s0 + s) * 625 + (size_t)(l * 5 + d)];
        #pragma unroll
        for (int h = 0; h < 5; h++)
            #pragma unroll
            for (int p = 0; p < 5; p++)
                hb[(h * 5 + p) * 25] = make_float2(fmaxf(f2lo(acc[h][p]), 0.f),
                                                   fmaxf(f2hi(acc[h][p]), 0.f));
    }
}

// ================= kernel 2: layer 2 =================
// 7 samples / 128-thr block; thread=(l,d,ocpair): 18 thr/sample (126/128
// lanes), computes 2 oc x 3h x 3w = 18 outputs. Even/odd lanes share hh
// addresses (broadcast pairs). Sample stride padded to 629 (= 5 mod 16
// 8B-banks) to de-overlap cross-sample bank clusters.
#define L2_SAMP 7
#define H1_STRIDE 629
__global__ __launch_bounds__(128)
void l2_kernel(const float* __restrict__ w2, const float* __restrict__ b2,
               float* __restrict__ out, int nsamp)
{
    __shared__ float2 h1s[L2_SAMP][H1_STRIDE];
    __shared__ __align__(16) float2 w2p[4][9][10]; // [oc][plane][tap pad]
    __shared__ float b2s[4];

    const int t  = threadIdx.x;
    const int s0 = blockIdx.x * L2_SAMP;

    for (int i = t; i < 324; i += 128) {
        int oc = i / 81, rr = i - oc * 81;
        int pl = rr / 9, tp = rr - pl * 9;
        w2p[oc][pl][tp] = make_float2(w2[oc * 162 + rr], w2[oc * 162 + 81 + rr]);
    }
    if (t < 4) b2s[t] = b2[t];

    {
        int nsm = nsamp - s0; if (nsm > L2_SAMP) nsm = L2_SAMP;
        int tot = nsm * 625;
        const float2* hg = &g_h1[(size_t)s0 * 625];
        for (int i = t; i < tot; i += 128) {
            int s = i / 625, r = i - s * 625;
            h1s[s][r] = hg[i];
        }
    }
    __syncthreads();

    const int s   = t / 18;
    const int tid = t - s * 18;
    if (t < 126 && s0 + s < nsamp) {
        const int pos = tid >> 1, ocp = tid & 1;
        const int l = pos / 3, d = pos - l * 3;
        const int oc0 = 2 * ocp;

        u64 acc[2][3][3];                       // [oc][h][w]
        #pragma unroll
        for (int c = 0; c < 2; c++) {
            u64 ini = pk2(b2s[oc0 + c], 0.f);
            #pragma unroll
            for (int h = 0; h < 3; h++)
                #pragma unroll
                for (int p = 0; p < 3; p++) acc[c][h][p] = ini;
        }

        #pragma unroll
        for (int i = 0; i < 3; i++)
        #pragma unroll
        for (int j = 0; j < 3; j++) {
            const int pl  = i * 3 + j;
            const int ldp = (l + i) * 5 + (d + j);
            const float2* vb = &h1s[s][ldp];

            u64 wr[2][9];
            #pragma unroll
            for (int c = 0; c < 2; c++) {
                const double2* wv = (const double2*)&w2p[oc0 + c][pl][0];
                double2 a0 = wv[0], a1 = wv[1], a2 = wv[2], a3 = wv[3];
                wr[c][0] = d2u(a0.x); wr[c][1] = d2u(a0.y);
                wr[c][2] = d2u(a1.x); wr[c][3] = d2u(a1.y);
                wr[c][4] = d2u(a2.x); wr[c][5] = d2u(a2.y);
                wr[c][6] = d2u(a3.x); wr[c][7] = d2u(a3.y);
                wr[c][8] = d2u(*(const double*)&w2p[oc0 + c][pl][8]);
            }

            #pragma unroll
            for (int r = 0; r < 5; r++) {
                u64 hh[5];
                #pragma unroll
                for (int q = 0; q < 5; q++)
                    hh[q] = d2u(*(const double*)(vb + (r * 5 + q) * 25));
                #pragma unroll
                for (int k = 0; k < 3; k++) {
                    const int h = r - k;
                    if (h >= 0 && h <= 2) {
                        #pragma unroll
                        for (int c = 0; c < 2; c++)
                        #pragma unroll
                        for (int m = 0; m < 3; m++) {
                            const u64 w = wr[c][k * 3 + m];
                            #pragma unroll
                            for (int p = 0; p < 3; p++)
                                acc[c][h][p] = ffma2(hh[p + m], w, acc[c][h][p]);
                        }
                    }
                }
            }
        }

        float* ob = out + (size_t)(s0 + s) * 324;
        #pragma unroll
        for (int c = 0; c < 2; c++)
            #pragma unroll
            for (int h = 0; h < 3; h++)
                #pragma unroll
                for (int p = 0; p < 3; p++)
                    ob[(oc0 + c) * 81 + ((l * 3 + d) * 3 + h) * 3 + p] =
                        fmaxf(f2lo(acc[c][h][p]) + f2hi(acc[c][h][p]), 0.f);
    }
}

extern "C" void kernel_launch(void* const* d_in, const int* in_sizes, int n_in,
                              void* d_out, int out_size) {
    const float* x  = (const float*)d_in[0];
    const float* w1 = (const float*)d_in[1];
    const float* b1 = (const float*)d_in[2];
    const float* w2 = (const float*)d_in[3];
    const float* b2 = (const float*)d_in[4];
    float* out = (float*)d_out;

    int n = in_sizes[0] / 2401;              // B
    if (n > MAX_B) n = MAX_B;
    l1_kernel<<<(n + 4) / 5, 128>>>(x, w1, b1, n);
    l2_kernel<<<(n + L2_SAMP - 1) / L2_SAMP, 128>>>(w2, b2, out, n);
}